// round 9
// baseline (speedup 1.0000x reference)
#include <cuda_runtime.h>
#include <math.h>
#include <stdint.h>

// Problem constants
#define Hd 1024
#define Vd 4096
#define Bd 64
#define Td 512
#define BT (Bd*Td)       // 32768
#define BdHd (Bd*Hd)
#define NBLK 128         // 4 groups x 32 CTAs
#define GSZ 32           // CTAs per group
#define GROWS 16         // batch rows per group
#define JPC 32           // j columns per CTA

// Scratch (device globals; no runtime allocation)
__device__ float g_abase[(size_t)BT*Hd];   // (t,b,h) pre-activation x_emb + b
__device__ float g_hs[(size_t)BT*Hd];      // (t,b,h) hidden states
__device__ unsigned g_gcnt[4*32];          // per-group barrier counters (128B apart)
__device__ unsigned g_ggen[4*32];          // per-group generations (128B apart)

// packed fp32x2 FMA (sm_100+; ptxas never auto-fuses this — PTX only)
__device__ __forceinline__ unsigned long long
fma2(unsigned long long a, unsigned long long b, unsigned long long c) {
    unsigned long long d;
    asm("fma.rn.f32x2 %0, %1, %2, %3;" : "=l"(d) : "l"(a), "l"(b), "l"(c));
    return d;
}
union F4U { float4 f4; unsigned long long u[2]; float f[4]; };

// ---------------------------------------------------------------------------
// K1: embedding gather + bias  a_base[(t*B+b), :] = wxh[X[b,t], :] + bvec
// ---------------------------------------------------------------------------
__global__ void embed_kernel(const int* __restrict__ X,
                             const float* __restrict__ wxh,
                             const float* __restrict__ bvec) {
    int r = blockIdx.x;            // r = t*B + b
    int t = r >> 6;
    int b = r & 63;
    int row = X[b * Td + t];
    const float4* src = (const float4*)(wxh + (size_t)row * Hd);
    const float4* bb  = (const float4*)bvec;
    float4* dst = (float4*)(g_abase + (size_t)r * Hd);
    int i = threadIdx.x;           // 256 = H/4
    float4 v = src[i];
    float4 w = bb[i];
    v.x += w.x; v.y += w.y; v.z += w.z; v.w += w.w;
    dst[i] = v;
}

// ---------------------------------------------------------------------------
// Group barrier: 32 CTAs of one group. Sense-reversing (count,gen) on
// group-private 128B-separated lines. Deterministic, graph-replay safe.
// ---------------------------------------------------------------------------
__device__ __forceinline__ void group_barrier(int tid, int grp) {
    __syncthreads();
    if (tid == 0) {
        unsigned* cnt = &g_gcnt[grp * 32];
        unsigned* gnp = &g_ggen[grp * 32];
        unsigned gen = *(volatile unsigned*)gnp;      // read BEFORE arrive
        __threadfence();                              // publish CTA's writes
        unsigned p = atomicAdd(cnt, 1u);
        if (p == GSZ - 1u) {
            atomicExch(cnt, 0u);                      // reset for next use
            __threadfence();
            atomicExch(gnp, gen + 1u);                // release
        } else {
            while (*(volatile unsigned*)gnp == gen) { }
        }
        __threadfence();                              // acquire
    }
    __syncthreads();
}

// ---------------------------------------------------------------------------
// K2: persistent recurrence, batch-partitioned groups. Same structure as R8
// (group g owns 16 batch rows; CTA jc holds its 32x1024 W_hh slice in smem;
// per step stage group's 16x1024 h slice; 16 warps = 8(j) x 2(b); lanes split
// K 32 ways; butterfly-shuffle reduce; tanh; 32-CTA group barrier) with ONE
// change: inner dot-products run on packed fma.rn.f32x2 (FFMA2), halving the
// fp32 issue floor 8192 -> 4096 cyc/SMSP/step.
// Swizzle (f4 units): phys(u) = u ^ ((u>>3)&7), rows stride 256 f4.
// ---------------------------------------------------------------------------
__global__ void __launch_bounds__(512, 1)
rnn_persistent(const float* __restrict__ whh) {
    extern __shared__ float4 dsm4[];
    float4* Wsl = dsm4;             // [32 rows][256 f4] swizzled  (128 KB)
    float4* hsm = dsm4 + 8192;      // [16 rows][256 f4] swizzled  (64 KB)

    const int bid = blockIdx.x;     // 0..127
    const int grp = bid >> 5;       // 0..3
    const int jc  = bid & 31;       // 0..31
    const int j0  = jc * JPC;
    const int b0  = grp * GROWS;
    const int tid = threadIdx.x;
    const int ln  = tid & 31;
    const int w   = tid >> 5;       // warp 0..15
    const int jw  = w >> 1;         // 0..7  (4 cols each)
    const int bw  = w & 1;          // 0..1  (8 rows each)

    // Load W_hh slice rows j0..j0+31 (contiguous) into swizzled smem
    {
        const float4* wsrc = (const float4*)(whh + (size_t)j0 * Hd);
        #pragma unroll
        for (int q = 0; q < 16; q++) {
            int idx = tid + q * 512;             // 0..8191
            int r = idx >> 8, u = idx & 255;
            Wsl[r * 256 + (u ^ ((u >> 3) & 7))] = wsrc[idx];
        }
    }

    // h_0 = tanh(a_base[0]) for this CTA's owned (b,j): 16x32 = 1/thread
    {
        int r = tid >> 5, cc = tid & 31;
        size_t off = (size_t)(b0 + r) * Hd + j0 + cc;
        g_hs[off] = tanhf(g_abase[off]);
    }

    // per-thread output coordinates (after shuffle reduce, lane ln owns
    // idx=ln -> (m = ln>>3, i = ln&7))
    const int jo = j0 + jw * 4 + (ln >> 3);
    const int bo = b0 + bw * 8 + (ln & 7);

    for (int t = 1; t < Td; t++) {
        group_barrier(tid, grp);   // h_{t-1} of group visible; guards hsm reuse

        // prefetch a_base for this thread's output (hides DRAM latency)
        float abv = __ldg(&g_abase[(size_t)t * BdHd + (size_t)bo * Hd + jo]);

        // stage group's h_{t-1} slice: 4096 f4, 8 per thread, coalesced
        {
            const float4* hsrc = (const float4*)(g_hs + (size_t)(t - 1) * BdHd
                                                      + (size_t)b0 * Hd);
            float4 pf[8];
            #pragma unroll
            for (int q = 0; q < 8; q++) pf[q] = hsrc[tid + q * 512];
            #pragma unroll
            for (int q = 0; q < 8; q++) {
                int idx = tid + q * 512;
                int r = idx >> 8, u = idx & 255;
                hsm[r * 256 + (u ^ ((u >> 3) & 7))] = pf[q];
            }
        }
        __syncthreads();

        // compute: thread covers j = jw*4..+4, b = bw*8..+8, k = ln*32..+32
        // acc2[e] packs partial sums over (even f32x2 lane, odd f32x2 lane)
        unsigned long long acc2[32];
        #pragma unroll
        for (int e = 0; e < 32; e++) acc2[e] = 0ull;   // (0.0f, 0.0f)

        #pragma unroll
        for (int kc = 0; kc < 8; kc++) {
            const int up = ln * 8 + (kc ^ (ln & 7));   // swizzled f4 col
            F4U wv[4];
            #pragma unroll
            for (int m = 0; m < 4; m++)
                wv[m].f4 = Wsl[(jw * 4 + m) * 256 + up];
            #pragma unroll
            for (int i = 0; i < 8; i++) {
                F4U hv;
                hv.f4 = hsm[(bw * 8 + i) * 256 + up];
                #pragma unroll
                for (int m = 0; m < 4; m++) {
                    unsigned long long s = acc2[m * 8 + i];
                    s = fma2(hv.u[0], wv[m].u[0], s);
                    s = fma2(hv.u[1], wv[m].u[1], s);
                    acc2[m * 8 + i] = s;
                }
            }
        }

        // collapse packed pairs -> scalar partials
        float acc[32];
        #pragma unroll
        for (int e = 0; e < 32; e++) {
            F4U u2; u2.u[0] = acc2[e];
            acc[e] = u2.f[0] + u2.f[1];
        }

        // butterfly shuffle reduction over 32 lanes (K partials).
        #pragma unroll
        for (int off = 16; off >= 1; off >>= 1) {
            #pragma unroll
            for (int i = 0; i < off; i++) {
                float send = (ln & off) ? acc[i] : acc[i + off];
                float keep = (ln & off) ? acc[i + off] : acc[i];
                acc[i] = keep + __shfl_xor_sync(0xffffffffu, send, off);
            }
        }
        // lane ln now holds the full K-sum for output (jo, bo)

        float hval = tanhf(acc[0] + abv);
        g_hs[(size_t)t * BdHd + (size_t)bo * Hd + jo] = hval;
        // group_barrier at next iteration guards hsm before overwrite
    }
}

// ---------------------------------------------------------------------------
// K4: output GEMM on tf32 tensor cores.
// z[r, v] = sum_k Hs[r,k] * Wvh[v,k] + c[v], row remap r=(t*B+b) -> (b*T+t).
// BM=128, BN=128, BK=16. 8 warps as 4(m) x 2(n); warp tile 32x64 =
// 2 x 8 tiles of m16n8k8. A row-major, B col-major (wvh rows ARE B columns).
// ---------------------------------------------------------------------------
__device__ __forceinline__ uint32_t f2tf32(float x) {
    uint32_t r;
    asm("cvt.rna.tf32.f32 %0, %1;" : "=r"(r) : "f"(x));
    return r;
}
__device__ __forceinline__ void mma_tf32(float c[4], uint32_t a0, uint32_t a1,
                                         uint32_t a2, uint32_t a3,
                                         uint32_t b0, uint32_t b1) {
    asm volatile(
        "mma.sync.aligned.m16n8k8.row.col.f32.tf32.tf32.f32 "
        "{%0,%1,%2,%3}, {%4,%5,%6,%7}, {%8,%9}, {%0,%1,%2,%3};"
        : "+f"(c[0]), "+f"(c[1]), "+f"(c[2]), "+f"(c[3])
        : "r"(a0), "r"(a1), "r"(a2), "r"(a3), "r"(b0), "r"(b1));
}

#define LDA 136   // pad: conflict-free fragment loads

__global__ void __launch_bounds__(256, 1)
vh_gemm_tf32(const float* __restrict__ wvh,
             const float* __restrict__ cvec,
             float* __restrict__ outp) {
    __shared__ uint32_t A_s[16][LDA];
    __shared__ uint32_t B_s[16][LDA];
    const int v0 = blockIdx.x * 128;
    const int r0 = blockIdx.y * 128;
    const int tid  = threadIdx.x;
    const int warp = tid >> 5;
    const int lane = tid & 31;
    const int warp_m = warp & 3;        // 4 m-warps
    const int warp_n = warp >> 2;       // 2 n-warps
    const int m_base = warp_m * 32;
    const int n_base = warp_n * 64;
    const int lq = lane >> 2;           // 0..7
    const int lr = lane & 3;            // 0..3

    float acc[2][8][4];
    #pragma unroll
    for (int mt = 0; mt < 2; mt++)
        #pragma unroll
        for (int nt = 0; nt < 8; nt++)
            #pragma unroll
            for (int e = 0; e < 4; e++) acc[mt][nt][e] = 0.0f;

    const int lrow = tid >> 2;          // 0..63
    const int lk4  = (tid & 3) * 4;

    for (int kc = 0; kc < 64; ++kc) {
        int k0 = kc * 16;
        float4 a0 = *(const float4*)(g_hs + (size_t)(r0 + lrow) * Hd + k0 + lk4);
        float4 a1 = *(const float4*)(g_hs + (size_t)(r0 + lrow + 64) * Hd + k0 + lk4);
        float4 b0 = *(const float4*)(wvh + (size_t)(v0 + lrow) * Hd + k0 + lk4);
        float4 b1 = *(const float4*)(wvh + (size_t)(v0 + lrow + 64) * Hd + k0 + lk4);
        __syncthreads();
        A_s[lk4 + 0][lrow] = f2tf32(a0.x); A_s[lk4 + 1][lrow] = f2tf32(a0.y);
        A_s[lk4 + 2][lrow] = f2tf32(a0.z); A_s[lk4 + 3][lrow] = f2tf32(a0.w);
        A_s[lk4 + 0][lrow + 64] = f2tf32(a1.x); A_s[lk4 + 1][lrow + 64] = f2tf32(a1.y);
        A_s[lk4 + 2][lrow + 64] = f2tf32(a1.z); A_s[lk4 + 3][lrow + 64] = f2tf32(a1.w);
        B_s[lk4 + 0][lrow] = f2tf32(b0.x); B_s[lk4 + 1][lrow] = f2tf32(b0.y);
        B_s[lk4 + 2][lrow] = f2tf32(b0.z); B_s[lk4 + 3][lrow] = f2tf32(b0.w);
        B_s[lk4 + 0][lrow + 64] = f2tf32(b1.x); B_s[lk4 + 1][lrow + 64] = f2tf32(b1.y);
        B_s[lk4 + 2][lrow + 64] = f2tf32(b1.z); B_s[lk4 + 3][lrow + 64] = f2tf32(b1.w);
        __syncthreads();

        #pragma unroll
        for (int ks = 0; ks < 2; ks++) {
            int kq = ks * 8 + lr;
            uint32_t afr[2][4];
            #pragma unroll
            for (int mt = 0; mt < 2; mt++) {
                int row = m_base + mt * 16 + lq;
                afr[mt][0] = A_s[kq][row];
                afr[mt][1] = A_s[kq][row + 8];
                afr[mt][2] = A_s[kq + 4][row];
                afr[mt][3] = A_s[kq + 4][row + 8];
            }
            uint32_t bfr[8][2];
            #pragma unroll
            for (int nt = 0; nt < 8; nt++) {
                int col = n_base + nt * 8 + lq;
                bfr[nt][0] = B_s[kq][col];
                bfr[nt][1] = B_s[kq + 4][col];
            }
            #pragma unroll
            for (int mt = 0; mt < 2; mt++)
                #pragma unroll
                for (int nt = 0; nt < 8; nt++)
                    mma_tf32(acc[mt][nt], afr[mt][0], afr[mt][1], afr[mt][2],
                             afr[mt][3], bfr[nt][0], bfr[nt][1]);
        }
    }

    // epilogue: add c, remap r=(t*B+b) -> (b*T+t), store float2 pairs
    #pragma unroll
    for (int nt = 0; nt < 8; nt++) {
        int col = n_base + nt * 8 + 2 * lr;
        float2 cv = *(const float2*)(cvec + v0 + col);
        #pragma unroll
        for (int mt = 0; mt < 2; mt++) {
            #pragma unroll
            for (int h = 0; h < 2; h++) {
                int r = r0 + m_base + mt * 16 + lq + h * 8;
                int orow = (r & 63) * Td + (r >> 6);   // b*T + t
                float2 o;
                o.x = acc[mt][nt][h * 2 + 0] + cv.x;
                o.y = acc[mt][nt][h * 2 + 1] + cv.y;
                *(float2*)(outp + (size_t)orow * Vd + v0 + col) = o;
            }
        }
    }
}

// ---------------------------------------------------------------------------
// K5: in-place log_softmax over rows of 4096. One block (256 thr) per row.
// ---------------------------------------------------------------------------
__global__ void logsoftmax_kernel(float* __restrict__ outp) {
    float* row = outp + (size_t)blockIdx.x * Vd;
    const int tid = threadIdx.x;
    const int lane = tid & 31;
    const int wid = tid >> 5;
    __shared__ float sred[8];

    float4 v[4];
    float mx = -1e30f;
    #pragma unroll
    for (int i = 0; i < 4; i++) {
        v[i] = *(const float4*)(row + (i * 256 + tid) * 4);
        mx = fmaxf(mx, fmaxf(fmaxf(v[i].x, v[i].y), fmaxf(v[i].z, v[i].w)));
    }
    #pragma unroll
    for (int o = 16; o; o >>= 1) mx = fmaxf(mx, __shfl_xor_sync(0xffffffffu, mx, o));
    if (lane == 0) sred[wid] = mx;
    __syncthreads();
    float m2 = sred[lane & 7];
    #pragma unroll
    for (int o = 4; o; o >>= 1) m2 = fmaxf(m2, __shfl_xor_sync(0xffffffffu, m2, o));
    mx = m2;
    __syncthreads();

    float sum = 0.0f;
    #pragma unroll
    for (int i = 0; i < 4; i++) {
        sum += expf(v[i].x - mx) + expf(v[i].y - mx)
             + expf(v[i].z - mx) + expf(v[i].w - mx);
    }
    #pragma unroll
    for (int o = 16; o; o >>= 1) sum += __shfl_xor_sync(0xffffffffu, sum, o);
    if (lane == 0) sred[wid] = sum;
    __syncthreads();
    float s2 = sred[lane & 7];
    #pragma unroll
    for (int o = 4; o; o >>= 1) s2 += __shfl_xor_sync(0xffffffffu, s2, o);

    float lse = mx + logf(s2);
    #pragma unroll
    for (int i = 0; i < 4; i++) {
        v[i].x -= lse; v[i].y -= lse; v[i].z -= lse; v[i].w -= lse;
        *(float4*)(row + (i * 256 + tid) * 4) = v[i];
    }
}

// ---------------------------------------------------------------------------
// K6: hiddens transpose  outh[h, r] = g_hs[r, h]   (r = t*B+b)
// ---------------------------------------------------------------------------
__global__ void transpose_kernel(float* __restrict__ outh) {
    __shared__ float tile[32][33];
    const int h0 = blockIdx.x * 32;
    const int r0 = blockIdx.y * 32;
    const int tx = threadIdx.x;
    const int ty = threadIdx.y;
    #pragma unroll
    for (int i = 0; i < 32; i += 8)
        tile[ty + i][tx] = g_hs[(size_t)(r0 + ty + i) * Hd + h0 + tx];
    __syncthreads();
    #pragma unroll
    for (int i = 0; i < 32; i += 8)
        outh[(size_t)(h0 + ty + i) * BT + r0 + tx] = tile[tx][ty + i];
}

// ---------------------------------------------------------------------------
extern "C" void kernel_launch(void* const* d_in, const int* in_sizes, int n_in,
                              void* d_out, int out_size) {
    const int*   X   = nullptr;
    const float* wxh = nullptr;
    const float* whh = nullptr;
    const float* wvh = nullptr;
    const float* bv  = nullptr;
    const float* cv  = nullptr;

    for (int i = 0; i < n_in; i++) {
        int s = in_sizes[i];
        if (s == BT && !X)            X   = (const int*)d_in[i];
        else if (s == Hd * Hd)        whh = (const float*)d_in[i];
        else if (s == Hd)             bv  = (const float*)d_in[i];
        else if (s == Vd)             cv  = (const float*)d_in[i];
        else if (s == Vd * Hd) {
            if (!wxh) wxh = (const float*)d_in[i];
            else      wvh = (const float*)d_in[i];
        }
    }

    float* outp = (float*)d_out;
    float* outs = outp;                       // (B, T, V) log-probs
    float* outh = outp + (size_t)BT * Vd;     // (H, T, B) hiddens

    // persistent kernel needs 192 KB dynamic smem (idempotent host call)
    const int rnn_smem = (8192 + 4096) * 16;  // 196,608 B
    cudaFuncSetAttribute(rnn_persistent,
                         cudaFuncAttributeMaxDynamicSharedMemorySize, rnn_smem);

    // 1) embedding gather + bias
    embed_kernel<<<BT, 256>>>(X, wxh, bv);
    // 2) recurrence: 4 independent batch groups, FFMA2 inner loops
    rnn_persistent<<<NBLK, 512, rnn_smem>>>(whh);
    // 3) output projection on tf32 tensor cores (writes z with row remap)
    vh_gemm_tf32<<<dim3(Vd / 128, BT / 128), 256>>>(wvh, cv, outs);
    // 4) log_softmax in place
    logsoftmax_kernel<<<BT, 256>>>(outs);
    // 5) hiddens transpose
    transpose_kernel<<<dim3(Hd / 32, BT / 32), dim3(32, 8)>>>(outh);
}